// round 1
// baseline (speedup 1.0000x reference)
#include <cuda_runtime.h>
#include <cstdint>

#define D_MODEL 1024
#define NE 64
#define NN 128          // route(64) || noise(64)
#define M_TOK 32768

// --- scratch (no allocations allowed) ---
__device__ __align__(16) float g_Wt[D_MODEL * NN];   // [k][j] k-major concat weights
__device__ __align__(16) float g_S[M_TOK * NN];      // [t][j] raw logits (no bias)

// ============================================================
// Kernel 0: transpose W_route/W_noise [64][1024] -> Wt[1024][128]
// ============================================================
__global__ void transpose_w_kernel(const float* __restrict__ Wr,
                                   const float* __restrict__ Wn) {
    int idx = blockIdx.x * blockDim.x + threadIdx.x;   // D_MODEL*NN = 131072
    int j = idx & (NN - 1);
    int k = idx >> 7;
    float v = (j < NE) ? Wr[j * D_MODEL + k] : Wn[(j - NE) * D_MODEL + k];
    g_Wt[k * NN + j] = v;
}

// ============================================================
// Kernel 1: SGEMM  g_S[M][128] = A[M][1024] * Wt[1024][128]
// BM=128, BN=128, BK=16, 128 threads, per-thread 8 rows x 16 cols
// accumulators as f32x2 (packed FMA doubles fp32 rate on sm_103a)
// ============================================================
#define BM 128
#define BK 16
#define ASTR 132   // padded [k][m] stride (floats), 16B aligned, conflict-free

__device__ __forceinline__ unsigned sptr(const void* p) {
    return (unsigned)__cvta_generic_to_shared(p);
}

__global__ void __launch_bounds__(128, 2)
gemm_kernel(const float* __restrict__ A) {
    __shared__ __align__(16) float As[2][BK * ASTR];
    __shared__ __align__(16) float Bs[2][BK * NN];

    const int tid = threadIdx.x;
    const int tr  = tid >> 3;       // 0..15 : row group (8 tokens)
    const int tc  = tid & 7;        // 0..7  : col group (16 cols, strided)
    const int m0  = blockIdx.x * BM;

    unsigned long long acc[8][8];   // [row][col-pair], f32x2
#pragma unroll
    for (int i = 0; i < 8; i++)
#pragma unroll
        for (int p = 0; p < 8; p++) acc[i][p] = 0ull;

    // A-tile loader mapping: thread loads 4 float4 (rows lrow+32r, k-quarter lchunk)
    const int lchunk = tid & 3;
    const int lrow   = tid >> 2;
    const float* abase = A + (size_t)(m0 + lrow) * D_MODEL + lchunk * 4;

    float4 areg[4];

    // ---- prologue: tile kt=0 ----
#pragma unroll
    for (int r = 0; r < 4; r++)
        areg[r] = *(const float4*)(abase + (size_t)(32 * r) * D_MODEL);
    {
        const float4* bsrc = (const float4*)(g_Wt);
#pragma unroll
        for (int r = 0; r < 4; r++) {
            int idx = tid + 128 * r;
            unsigned dst = sptr(&Bs[0][idx * 4]);
            asm volatile("cp.async.ca.shared.global [%0], [%1], 16;"
                         :: "r"(dst), "l"(bsrc + idx));
        }
        asm volatile("cp.async.commit_group;");
    }
#pragma unroll
    for (int r = 0; r < 4; r++) {
        float4 v = areg[r];
        float* d = &As[0][lchunk * 4 * ASTR + lrow + 32 * r];
        d[0] = v.x; d[ASTR] = v.y; d[2 * ASTR] = v.z; d[3 * ASTR] = v.w;
    }
    asm volatile("cp.async.wait_group 0;");
    __syncthreads();

    int buf = 0;
    const int NT = D_MODEL / BK;    // 64
    for (int kt = 0; kt < NT; kt++) {
        if (kt + 1 < NT) {
            const float* ab = abase + (kt + 1) * BK;
#pragma unroll
            for (int r = 0; r < 4; r++)
                areg[r] = *(const float4*)(ab + (size_t)(32 * r) * D_MODEL);
            const float4* bsrc = (const float4*)(g_Wt + (size_t)(kt + 1) * BK * NN);
            int nb = buf ^ 1;
#pragma unroll
            for (int r = 0; r < 4; r++) {
                int idx = tid + 128 * r;
                unsigned dst = sptr(&Bs[nb][idx * 4]);
                asm volatile("cp.async.ca.shared.global [%0], [%1], 16;"
                             :: "r"(dst), "l"(bsrc + idx));
            }
            asm volatile("cp.async.commit_group;");
        }

        // ---- compute on current buffer ----
        {
            const float* asb = As[buf];
            unsigned bb = sptr(&Bs[buf][0]) + tc * 16;
#pragma unroll
            for (int k = 0; k < BK; k++) {
                float4 a0 = *(const float4*)(asb + k * ASTR + tr * 8);
                float4 a1 = *(const float4*)(asb + k * ASTR + tr * 8 + 4);
                unsigned long long ad[8];
                asm("mov.b64 %0,{%1,%1};" : "=l"(ad[0]) : "f"(a0.x));
                asm("mov.b64 %0,{%1,%1};" : "=l"(ad[1]) : "f"(a0.y));
                asm("mov.b64 %0,{%1,%1};" : "=l"(ad[2]) : "f"(a0.z));
                asm("mov.b64 %0,{%1,%1};" : "=l"(ad[3]) : "f"(a0.w));
                asm("mov.b64 %0,{%1,%1};" : "=l"(ad[4]) : "f"(a1.x));
                asm("mov.b64 %0,{%1,%1};" : "=l"(ad[5]) : "f"(a1.y));
                asm("mov.b64 %0,{%1,%1};" : "=l"(ad[6]) : "f"(a1.z));
                asm("mov.b64 %0,{%1,%1};" : "=l"(ad[7]) : "f"(a1.w));
                unsigned long long bq[8];
#pragma unroll
                for (int q = 0; q < 4; q++) {
                    asm volatile("ld.shared.v2.b64 {%0,%1},[%2];"
                                 : "=l"(bq[2 * q]), "=l"(bq[2 * q + 1])
                                 : "r"(bb + k * 512 + q * 128));
                }
#pragma unroll
                for (int i = 0; i < 8; i++)
#pragma unroll
                    for (int p = 0; p < 8; p++)
                        asm("fma.rn.f32x2 %0,%1,%2,%0;"
                            : "+l"(acc[i][p]) : "l"(ad[i]), "l"(bq[p]));
            }
        }

        if (kt + 1 < NT) {
            int nb = buf ^ 1;
#pragma unroll
            for (int r = 0; r < 4; r++) {
                float4 v = areg[r];
                float* d = &As[nb][lchunk * 4 * ASTR + lrow + 32 * r];
                d[0] = v.x; d[ASTR] = v.y; d[2 * ASTR] = v.z; d[3 * ASTR] = v.w;
            }
            asm volatile("cp.async.wait_group 0;");
        }
        __syncthreads();
        buf ^= 1;
    }

    // ---- store logits to scratch ----
#pragma unroll
    for (int i = 0; i < 8; i++) {
        float* orow = g_S + (size_t)(m0 + tr * 8 + i) * NN;
#pragma unroll
        for (int q = 0; q < 4; q++) {
            *(float2*)(orow + tc * 4 + q * 32)     = *(float2*)&acc[i][2 * q];
            *(float2*)(orow + tc * 4 + q * 32 + 2) = *(float2*)&acc[i][2 * q + 1];
        }
    }
}

// ============================================================
// Kernel 2: warp-per-token noisy top-2 router epilogue
// ============================================================
__global__ void router_epilogue(const float* __restrict__ noise,
                                const float* __restrict__ br,
                                const float* __restrict__ bn,
                                float* __restrict__ out,
                                int M, int write_idx) {
    int warp = (blockIdx.x * blockDim.x + threadIdx.x) >> 5;
    int lane = threadIdx.x & 31;
    if (warp >= M) return;

    const float* srow = g_S + (size_t)warp * NN;
    int e0 = lane, e1 = lane + 32;

    float r0 = srow[e0]      + br[e0];
    float r1 = srow[e1]      + br[e1];
    float n0 = srow[64 + e0] + bn[e0];
    float n1 = srow[64 + e1] + bn[e1];

    float sp0 = fmaxf(n0, 0.f) + log1pf(expf(-fabsf(n0)));
    float sp1 = fmaxf(n1, 0.f) + log1pf(expf(-fabsf(n1)));

    float z0 = r0 + noise[(size_t)warp * NE + e0] * sp0;
    float z1 = r1 + noise[(size_t)warp * NE + e1] * sp1;

    // local sorted top-2 (ties -> lower index first; e0 < e1)
    float v1, v2; int i1, i2;
    if (z1 > z0) { v1 = z1; i1 = e1; v2 = z0; i2 = e0; }
    else         { v1 = z0; i1 = e0; v2 = z1; i2 = e1; }

    // butterfly merge of sorted pairs, jax top_k tie-break (lower index wins)
#pragma unroll
    for (int off = 16; off > 0; off >>= 1) {
        float w1 = __shfl_xor_sync(0xffffffffu, v1, off);
        int   j1 = __shfl_xor_sync(0xffffffffu, i1, off);
        float w2 = __shfl_xor_sync(0xffffffffu, v2, off);
        int   j2 = __shfl_xor_sync(0xffffffffu, i2, off);
        bool bwins = (w1 > v1) || (w1 == v1 && j1 < i1);
        if (bwins) {
            float c2v; int c2i;
            if ((v1 > w2) || (v1 == w2 && i1 < j2)) { c2v = v1; c2i = i1; }
            else                                    { c2v = w2; c2i = j2; }
            v1 = w1; i1 = j1; v2 = c2v; i2 = c2i;
        } else {
            if ((w1 > v2) || (w1 == v2 && j1 < i2)) { v2 = w1; i2 = j1; }
        }
    }

    float ex  = expf(v2 - v1);
    float inv = 1.f / (1.f + ex);
    float p1 = inv, p2 = ex * inv;

    float* orow = out + (size_t)warp * NE;
    orow[e0] = (e0 == i1) ? p1 : ((e0 == i2) ? p2 : 0.f);
    orow[e1] = (e1 == i1) ? p1 : ((e1 == i2) ? p2 : 0.f);

    if (write_idx && lane == 0) {
        float* iout = out + (size_t)M * NE + (size_t)warp * 2;
        iout[0] = (float)i1;
        iout[1] = (float)i2;
    }
}

// ============================================================
extern "C" void kernel_launch(void* const* d_in, const int* in_sizes, int n_in,
                              void* d_out, int out_size) {
    const float* mh    = (const float*)d_in[0];
    const float* noise = (const float*)d_in[1];
    const float* Wr    = (const float*)d_in[2];
    const float* br    = (const float*)d_in[3];
    const float* Wn    = (const float*)d_in[4];
    const float* bn    = (const float*)d_in[5];
    float* out = (float*)d_out;

    int M = in_sizes[0] / D_MODEL;           // 32768
    if (M > M_TOK) M = M_TOK;

    transpose_w_kernel<<<(D_MODEL * NN) / 256, 256>>>(Wr, Wn);
    gemm_kernel<<<M / BM, 128>>>(mh);

    int write_idx = (out_size >= M * NE + M * 2) ? 1 : 0;
    router_epilogue<<<(M * 32) / 256, 256>>>(noise, br, bn, out, M, write_idx);
}

// round 3
// speedup vs baseline: 1.6185x; 1.6185x over previous
#include <cuda_runtime.h>
#include <cuda_fp16.h>
#include <cstdint>

#define D_MODEL 1024
#define NE 64
#define NN 128
#define BM 128
#define BK 64               // fp32 K per chunk
#define NCH (D_MODEL / BK)  // 16
#define ABYTES 16384        // 128 rows x 128B (64 f16)
#define BBYTES 16384        // 64 rows x 256B (128 f16)
#define SMEM_BYTES 131072   // A: [2buf][2split][16KB] @0, B: [2buf][2split][16KB] @65536
#define CSTRIDE 132         // epilogue C stride (floats), 16B aligned rows

// pre-split, pre-swizzled weights: [split][chunk] 16KB images
__device__ __align__(128) unsigned char g_Bf[2 * NCH * BBYTES];

// swizzles (XOR bits 4-6 with row&7)
#define SWZB(r, c) ((r) * 256 + ((c) ^ (((r) & 7) << 4)))   // 256B rows (B image)

__device__ __forceinline__ uint32_t smem_u32(const void* p) {
    uint32_t a;
    asm("{ .reg .u64 t; cvta.to.shared.u64 t, %1; cvt.u32.u64 %0, t; }" : "=r"(a) : "l"(p));
    return a;
}
#define CP16(dst, src) asm volatile("cp.async.ca.shared.global [%0], [%1], 16;" :: "r"(dst), "l"(src))
#define CP_COMMIT()    asm volatile("cp.async.commit_group;")
#define CP_WAIT0()     asm volatile("cp.async.wait_group 0;")

#define LDSM4(r, p) \
    asm volatile("ldmatrix.sync.aligned.m8n8.x4.shared.b16 {%0,%1,%2,%3}, [%4];" \
                 : "=r"((r)[0]), "=r"((r)[1]), "=r"((r)[2]), "=r"((r)[3]) : "r"(p))
#define LDSM4T(r, p) \
    asm volatile("ldmatrix.sync.aligned.m8n8.x4.trans.shared.b16 {%0,%1,%2,%3}, [%4];" \
                 : "=r"((r)[0]), "=r"((r)[1]), "=r"((r)[2]), "=r"((r)[3]) : "r"(p))
#define MMA16816(d, a, b0, b1) \
    asm volatile("mma.sync.aligned.m16n8k16.row.col.f32.f16.f16.f32 " \
                 "{%0,%1,%2,%3}, {%4,%5,%6,%7}, {%8,%9}, {%0,%1,%2,%3};" \
                 : "+f"((d)[0]), "+f"((d)[1]), "+f"((d)[2]), "+f"((d)[3]) \
                 : "r"((a)[0]), "r"((a)[1]), "r"((a)[2]), "r"((a)[3]), "r"(b0), "r"(b1))

// ============================================================
// Prep: fp16 2-split of W_route||W_noise into swizzled k-chunk images
// ============================================================
__global__ void prep_w(const float* __restrict__ Wr, const float* __restrict__ Wn) {
    int idx = blockIdx.x * blockDim.x + threadIdx.x;   // 65536: k x n-pairs
    int k = idx >> 6;
    int n = (idx & 63) * 2;

    float x = (n < NE) ? Wr[n * D_MODEL + k] : Wn[(n - NE) * D_MODEL + k];
    float y = (n + 1 < NE) ? Wr[(n + 1) * D_MODEL + k] : Wn[(n + 1 - NE) * D_MODEL + k];

    __half2 h0 = __floats2half2_rn(x, y);
    float2 f0 = __half22float2(h0);
    __half2 h1 = __floats2half2_rn(x - f0.x, y - f0.y);

    int c = k >> 6, kr = k & 63;
    uint32_t off = SWZB(kr, n * 2);
    *(uint32_t*)(g_Bf + ((size_t)c << 14) + off) = reinterpret_cast<uint32_t&>(h0);
    *(uint32_t*)(g_Bf + (((size_t)(NCH + c)) << 14) + off) = reinterpret_cast<uint32_t&>(h1);
}

// ============================================================
// Fused split-fp16 HMMA GEMM + noisy top-2 router epilogue
// ============================================================
__device__ __forceinline__ void split_pack8(float4 a, float4 b, uint4& s0, uint4& s1) {
    __half2 p0 = __floats2half2_rn(a.x, a.y);
    __half2 p1 = __floats2half2_rn(a.z, a.w);
    __half2 p2 = __floats2half2_rn(b.x, b.y);
    __half2 p3 = __floats2half2_rn(b.z, b.w);
    float2 f0 = __half22float2(p0), f1 = __half22float2(p1);
    float2 f2 = __half22float2(p2), f3 = __half22float2(p3);
    __half2 q0 = __floats2half2_rn(a.x - f0.x, a.y - f0.y);
    __half2 q1 = __floats2half2_rn(a.z - f1.x, a.w - f1.y);
    __half2 q2 = __floats2half2_rn(b.x - f2.x, b.y - f2.y);
    __half2 q3 = __floats2half2_rn(b.z - f3.x, b.w - f3.y);
    s0.x = reinterpret_cast<uint32_t&>(p0); s0.y = reinterpret_cast<uint32_t&>(p1);
    s0.z = reinterpret_cast<uint32_t&>(p2); s0.w = reinterpret_cast<uint32_t&>(p3);
    s1.x = reinterpret_cast<uint32_t&>(q0); s1.y = reinterpret_cast<uint32_t&>(q1);
    s1.z = reinterpret_cast<uint32_t&>(q2); s1.w = reinterpret_cast<uint32_t&>(q3);
}

__global__ void __launch_bounds__(256, 1)
moe_mma(const float* __restrict__ A, const float* __restrict__ noise,
        const float* __restrict__ br, const float* __restrict__ bn,
        float* __restrict__ out, int M, int write_idx) {
    extern __shared__ __align__(128) unsigned char smem[];
    __shared__ float bias[NN];
    const uint32_t sb = smem_u32(smem);
    const int tid = threadIdx.x;
    const int w = tid >> 5, l = tid & 31;
    const int m0 = blockIdx.x * BM;

    if (tid < NN) bias[tid] = (tid < NE) ? br[tid] : bn[tid - NE];

    const int wm = (w & 3) * 32;          // warp row base
    const int n0 = (w >> 2) * 64;         // warp col base

    // ldmatrix per-lane precomputes
    const int l16 = l & 15;
    const uint32_t khalf16 = (uint32_t)((l >> 4) << 4);
    const uint32_t Ra  = (uint32_t)(wm + l16) * 128;       // A row byte (mt=0)
    const uint32_t rxa = ((uint32_t)((wm + l16) & 7)) << 4;
    const uint32_t Rb0 = (uint32_t)l16 * 256;              // B row byte (ks=0)
    const uint32_t rxb = ((uint32_t)(l16 & 7)) << 4;
    const uint32_t cbb = (uint32_t)(n0 * 2) + khalf16;     // B col byte base

    // A loader mapping: 2 threads per row, 32 fp32 each
    const int arow = tid >> 1, ahalf = tid & 1;
    const float* aptr = A + (size_t)(m0 + arow) * D_MODEL + ahalf * 32;
    const uint32_t arow_rx = ((uint32_t)(arow & 7)) << 4;
    const uint32_t a_st_row = (uint32_t)arow * 128;

    float acc[2][8][4];
#pragma unroll
    for (int i = 0; i < 2; i++)
#pragma unroll
        for (int j = 0; j < 8; j++)
#pragma unroll
            for (int q = 0; q < 4; q++) acc[i][j][q] = 0.f;

    float4 av[8];

    auto ldg_a = [&](int c) {
#pragma unroll
        for (int i = 0; i < 8; i++) av[i] = *(const float4*)(aptr + c * BK + i * 4);
    };
    auto cp_b = [&](int c, int buf) {
#pragma unroll
        for (int s = 0; s < 2; s++) {
            const unsigned char* src = g_Bf + (((size_t)(s * NCH + c)) << 14);
            uint32_t dst = sb + 65536 + buf * 32768 + s * 16384;
#pragma unroll
            for (int j = 0; j < 4; j++) {
                uint32_t o = (uint32_t)(tid + j * 256) * 16;
                CP16(dst + o, src + o);
            }
        }
        CP_COMMIT();
    };
    auto sts_a = [&](int buf) {
        unsigned char* base0 = smem + buf * 32768;
        unsigned char* base1 = base0 + 16384;
#pragma unroll
        for (int q = 0; q < 4; q++) {
            uint4 s0, s1;
            split_pack8(av[2 * q], av[2 * q + 1], s0, s1);
            uint32_t phys = a_st_row + (((uint32_t)(ahalf * 64 + q * 16)) ^ arow_rx);
            *(uint4*)(base0 + phys) = s0;
            *(uint4*)(base1 + phys) = s1;
        }
    };

    // prologue
    ldg_a(0);
    cp_b(0, 0);
    sts_a(0);
    CP_WAIT0();
    __syncthreads();

    for (int c = 0; c < NCH; c++) {
        int buf = c & 1;
        if (c + 1 < NCH) { ldg_a(c + 1); cp_b(c + 1, buf ^ 1); }

        uint32_t Ab = sb + buf * 32768;
        uint32_t Bb = sb + 65536 + buf * 32768;
#pragma unroll
        for (int ks = 0; ks < 4; ks++) {
            uint32_t ca = ((uint32_t)(ks * 32) + khalf16) ^ rxa;
            uint32_t a0f[2][4], a1f[2][4];
            LDSM4(a0f[0], Ab + Ra + ca);
            LDSM4(a0f[1], Ab + Ra + 2048 + ca);
            LDSM4(a1f[0], Ab + 16384 + Ra + ca);
            LDSM4(a1f[1], Ab + 16384 + Ra + 2048 + ca);

            uint32_t Rb = Rb0 + (uint32_t)ks * 4096;
            uint32_t b0f[4][4], b1f[4][4];
#pragma unroll
            for (int nt = 0; nt < 4; nt++) {
                uint32_t cc = (cbb + (uint32_t)(nt * 32)) ^ rxb;
                LDSM4T(b0f[nt], Bb + Rb + cc);
                LDSM4T(b1f[nt], Bb + 16384 + Rb + cc);
            }
#pragma unroll
            for (int mt = 0; mt < 2; mt++)
#pragma unroll
                for (int nt = 0; nt < 4; nt++) {
                    MMA16816(acc[mt][2 * nt],     a0f[mt], b0f[nt][0], b0f[nt][1]);
                    MMA16816(acc[mt][2 * nt + 1], a0f[mt], b0f[nt][2], b0f[nt][3]);
                    MMA16816(acc[mt][2 * nt],     a0f[mt], b1f[nt][0], b1f[nt][1]);
                    MMA16816(acc[mt][2 * nt + 1], a0f[mt], b1f[nt][2], b1f[nt][3]);
                    MMA16816(acc[mt][2 * nt],     a1f[mt], b0f[nt][0], b0f[nt][1]);
                    MMA16816(acc[mt][2 * nt + 1], a1f[mt], b0f[nt][2], b0f[nt][3]);
                }
        }

        if (c + 1 < NCH) { sts_a(buf ^ 1); CP_WAIT0(); }
        __syncthreads();
    }

    // ---- epilogue: accs -> SMEM C [128][CSTRIDE] ----
    float* C = (float*)smem;
    {
        int r0 = wm + (l >> 2);
        int cb = n0 + (l & 3) * 2;
#pragma unroll
        for (int mt = 0; mt < 2; mt++)
#pragma unroll
            for (int j = 0; j < 8; j++) {
                int rr = r0 + mt * 16;
                int cc = cb + j * 8;
                *(float2*)(C + rr * CSTRIDE + cc)       = *(float2*)&acc[mt][j][0];
                *(float2*)(C + (rr + 8) * CSTRIDE + cc) = *(float2*)&acc[mt][j][2];
            }
    }
    __syncthreads();

    if (tid < BM) {
        const int token = m0 + tid;
        const float* crow = C + tid * CSTRIDE;
        const float* nrow = noise + (size_t)token * NE;
        float nz[NE];
#pragma unroll
        for (int q = 0; q < NE / 4; q++) *(float4*)(nz + q * 4) = *(const float4*)(nrow + q * 4);

        float v1 = -1e30f, v2 = -1e30f;
        int i1 = 0, i2 = 0;
#pragma unroll 8
        for (int e = 0; e < NE; e++) {
            float rl  = crow[e] + bias[e];
            float nlg = crow[NE + e] + bias[NE + e];
            float sp  = fmaxf(nlg, 0.f) + log1pf(expf(-fabsf(nlg)));
            float z   = rl + nz[e] * sp;
            if (z > v1)      { v2 = v1; i2 = i1; v1 = z; i1 = e; }
            else if (z > v2) { v2 = z; i2 = e; }
        }

        float ex  = expf(v2 - v1);
        float inv = 1.f / (1.f + ex);
        float p1 = inv, p2 = ex * inv;

        float* orow = out + (size_t)token * NE;
        float4 zf = make_float4(0.f, 0.f, 0.f, 0.f);
#pragma unroll
        for (int q = 0; q < NE / 4; q++) *(float4*)(orow + q * 4) = zf;
        orow[i1] = p1;
        orow[i2] = p2;

        if (write_idx) {
            float2 iv = make_float2((float)i1, (float)i2);
            *(float2*)(out + (size_t)M * NE + (size_t)token * 2) = iv;
        }
    }
}

// ============================================================
extern "C" void kernel_launch(void* const* d_in, const int* in_sizes, int n_in,
                              void* d_out, int out_size) {
    const float* mh    = (const float*)d_in[0];
    const float* noise = (const float*)d_in[1];
    const float* Wr    = (const float*)d_in[2];
    const float* br    = (const float*)d_in[3];
    const float* Wn    = (const float*)d_in[4];
    const float* bn    = (const float*)d_in[5];
    float* out = (float*)d_out;

    int M = in_sizes[0] / D_MODEL;   // 32768

    cudaFuncSetAttribute(moe_mma, cudaFuncAttributeMaxDynamicSharedMemorySize, SMEM_BYTES);

    prep_w<<<(D_MODEL * NN / 2) / 256, 256>>>(Wr, Wn);

    int write_idx = (out_size >= M * NE + M * 2) ? 1 : 0;
    moe_mma<<<M / BM, 256, SMEM_BYTES>>>(mh, noise, br, bn, out, M, write_idx);
}